// round 7
// baseline (speedup 1.0000x reference)
#include <cuda_runtime.h>
#include <cuda_bf16.h>
#include <cuda_fp16.h>

#define NN   100000
#define NE   1600000
#define NG   4096
#define HID  128
#define FIN  11
#define FPAD 16
#define FOUT 19
#define NT   (NE + NN)   // edges + self loops
#define SCAN_B 1024
#define NB   ((NN + SCAN_B - 1) / SCAN_B)   // 98
#define EDGE_BLKS ((NE + 255) / 256)        // 6250
#define FUSE_BLKS 10
#define POOL_BLKS ((NG * HID) / 256)        // 2048
#define NPW  8           // nodes per warp in agg2
#define G2_NPW 25        // nodes per warp in gemm1 (500*8*25 = 100000)
#define G2_BLK 500

// ---- scratch (static device globals; no allocation) ----
// Invariant: g_cnt and g_gcnt are all-zero at entry (BSS zero on first call;
// reset inside scanA/scanB each call). g_pool zeroed by k_deg tail blocks.
__device__ int   g_cnt[NN];
__device__ float g_dinv[NN];
__device__ int   g_off[NN + 1];      // block-LOCAL exclusive offsets
__device__ int   g_cur[NN];          // block-LOCAL cursors
__device__ int   g_col[NT];
__device__ int   g_bsum[NB];
__device__ int   g_bpre[NB];         // block prefixes (add to local offsets)
__device__ int   g_gcnt[NG];
__device__ int   g_gstart[NG + 1];   // node range per graph (batch is sorted)
__device__ __align__(16) __half g_xsh[NN * FPAD];   // dinv[i]*x[i], fp16, padded
__device__ __align__(16) float g_agg1[NN * FPAD];
__device__ __align__(16) unsigned int g_h1q[NN * 32]; // int8 rows, 128 B each
__device__ float g_hscl[NN];                          // per-row dequant scale (dinv folded)
__device__ __align__(16) float g_pool[NG * HID];
__device__ float g_wf[HID * FOUT];
__device__ float g_bf[FOUT];

// ---- deg (edge blocks) + fused weight precompute + pool zeroing (tail blocks) ----
__global__ void k_deg(const int* __restrict__ dst,
                      const float* __restrict__ W2, const float* __restrict__ Wlin,
                      const float* __restrict__ b2, const float* __restrict__ blin) {
    int b = blockIdx.x;
    if (b < EDGE_BLKS) {
        int e = b * 256 + threadIdx.x;
        if (e < NE) atomicAdd(&g_cnt[dst[e]], 1);
    } else if (b < EDGE_BLKS + POOL_BLKS) {
        int t = (b - EDGE_BLKS) * 256 + threadIdx.x;
        g_pool[t] = 0.0f;
    } else {
        int t = (b - EDGE_BLKS - POOL_BLKS) * 256 + threadIdx.x;
        if (t < HID * FOUT) {
            int f = t / FOUT, o = t % FOUT;
            float acc = 0.0f;
            for (int m = 0; m < HID; m++) acc += W2[f * HID + m] * Wlin[m * FOUT + o];
            g_wf[t] = acc;
        }
        if (t < FOUT) {
            float acc = blin[t];
            for (int m = 0; m < HID; m++) acc += b2[m] * Wlin[m * FOUT + t];
            g_bf[t] = acc;
        }
    }
}

// ---- scanA: per-block local scan of (deg+1), fused dinv/xs/graph-count; resets g_cnt ----
__global__ void k_scanA(const int* __restrict__ batch, const float* __restrict__ x) {
    __shared__ int s[SCAN_B];
    int t = threadIdx.x;
    int i = blockIdx.x * SCAN_B + t;
    int c = 0;
    if (i < NN) {
        c = g_cnt[i] + 1;              // +1 self-loop
        g_cnt[i] = 0;                  // restore invariant for next call
        float di = rsqrtf((float)c);
        g_dinv[i] = di;
        atomicAdd(&g_gcnt[batch[i]], 1);
        __half* row = &g_xsh[i * FPAD];
#pragma unroll
        for (int k = 0; k < FIN; k++) row[k] = __float2half(di * x[i * FIN + k]);
#pragma unroll
        for (int k = FIN; k < FPAD; k++) row[k] = __float2half(0.0f);
    }
    s[t] = c;
    __syncthreads();
#pragma unroll
    for (int off = 1; off < SCAN_B; off <<= 1) {
        int v = (t >= off) ? s[t - off] : 0;
        __syncthreads();
        if (t >= off) s[t] += v;
        __syncthreads();
    }
    if (i < NN) { g_off[i] = s[t] - c; g_cur[i] = s[t] - c; }
    else if (i == NN) g_off[NN] = s[t];   // c==0 → local total
    if (t == SCAN_B - 1) g_bsum[blockIdx.x] = s[t];
}

// ---- scanB: scan block sums -> g_bpre; scan g_gcnt -> g_gstart; resets g_gcnt ----
__global__ void k_scanB() {
    __shared__ int s[1024];
    int t = threadIdx.x;
    int v = (t < NB) ? g_bsum[t] : 0;
    s[t] = v;
    __syncthreads();
#pragma unroll
    for (int off = 1; off < 1024; off <<= 1) {
        int u = (t >= off) ? s[t - off] : 0;
        __syncthreads();
        if (t >= off) s[t] += u;
        __syncthreads();
    }
    if (t < NB) g_bpre[t] = s[t] - v;
    __syncthreads();
    int base = t * 4;
    int c0 = g_gcnt[base + 0], c1 = g_gcnt[base + 1];
    int c2 = g_gcnt[base + 2], c3 = g_gcnt[base + 3];
    g_gcnt[base + 0] = 0; g_gcnt[base + 1] = 0;
    g_gcnt[base + 2] = 0; g_gcnt[base + 3] = 0;
    int tsum = c0 + c1 + c2 + c3;
    s[t] = tsum;
    __syncthreads();
#pragma unroll
    for (int off = 1; off < 1024; off <<= 1) {
        int u = (t >= off) ? s[t - off] : 0;
        __syncthreads();
        if (t >= off) s[t] += u;
        __syncthreads();
    }
    int excl = s[t] - tsum;
    g_gstart[base + 0] = excl;
    g_gstart[base + 1] = excl + c0;
    g_gstart[base + 2] = excl + c0 + c1;
    g_gstart[base + 3] = excl + c0 + c1 + c2;
    if (t == 1023) g_gstart[NG] = s[t];   // == NN
}

__global__ void k_fill(const int* __restrict__ src, const int* __restrict__ dst) {
    int t = blockIdx.x * blockDim.x + threadIdx.x;
    if (t >= NT) return;
    int s, d;
    if (t < NE) { s = src[t]; d = dst[t]; }
    else        { s = d = t - NE; }
    int p = atomicAdd(&g_cur[d], 1) + g_bpre[d >> 10];
    g_col[p] = s;
}

// agg1[i] = dinv[i] * sum_j xs[col[j]]; lane = 8*e + f
__global__ void k_agg1() {
    int warp = (blockIdx.x * blockDim.x + threadIdx.x) >> 5;
    int lane = threadIdx.x & 31;
    if (warp >= NN) return;
    int beg = g_off[warp] + g_bpre[warp >> 10];
    int end = g_off[warp + 1] + g_bpre[(warp + 1) >> 10];
    int e = lane >> 3, f = lane & 7;
    const __half2* xs2 = (const __half2*)g_xsh;
    float2 acc = make_float2(0.f, 0.f);
    for (int j = beg + e; j < end; j += 4) {
        float2 a = __half22float2(xs2[g_col[j] * 8 + f]);
        acc.x += a.x; acc.y += a.y;
    }
    acc.x += __shfl_xor_sync(0xffffffff, acc.x, 8);
    acc.y += __shfl_xor_sync(0xffffffff, acc.y, 8);
    acc.x += __shfl_xor_sync(0xffffffff, acc.x, 16);
    acc.y += __shfl_xor_sync(0xffffffff, acc.y, 16);
    if (lane < 8) {
        float di = g_dinv[warp];
        ((float2*)&g_agg1[warp * FPAD])[f] = make_float2(di * acc.x, di * acc.y);
    }
}

// gemm1: warp per node, lane owns 4 output features.
// v = relu(agg1 @ W1 + b1); quantize row to int8 (q = v * 127/vmax),
// store scale = dinv * vmax / 127 (dinv folded into scale, not values).
__global__ void k_gemm1(const float* __restrict__ W1, const float* __restrict__ b1) {
    __shared__ float sW[FIN * HID];
    int t = threadIdx.x;
    for (int k = t; k < FIN * HID; k += 256) sW[k] = W1[k];
    __syncthreads();
    int lane = t & 31;
    int w = blockIdx.x * 8 + (t >> 5);
    int n0 = w * G2_NPW;
    float4 bl = ((const float4*)b1)[lane];
    float wc[FIN][4];
#pragma unroll
    for (int k = 0; k < FIN; k++) {
#pragma unroll
        for (int c = 0; c < 4; c++) wc[k][c] = sW[k * HID + 4 * lane + c];
    }
    for (int node = n0; node < n0 + G2_NPW; node++) {
        const float4* ar = (const float4*)&g_agg1[node * FPAD];
        float4 a0 = ar[0], a1 = ar[1], a2 = ar[2];   // broadcast loads
        float a[FIN] = {a0.x, a0.y, a0.z, a0.w, a1.x, a1.y, a1.z, a1.w,
                        a2.x, a2.y, a2.z};
        float v0 = bl.x, v1 = bl.y, v2 = bl.z, v3 = bl.w;
#pragma unroll
        for (int k = 0; k < FIN; k++) {
            v0 += a[k] * wc[k][0];
            v1 += a[k] * wc[k][1];
            v2 += a[k] * wc[k][2];
            v3 += a[k] * wc[k][3];
        }
        v0 = fmaxf(v0, 0.f); v1 = fmaxf(v1, 0.f);
        v2 = fmaxf(v2, 0.f); v3 = fmaxf(v3, 0.f);
        float m = fmaxf(fmaxf(v0, v1), fmaxf(v2, v3));
#pragma unroll
        for (int off = 16; off > 0; off >>= 1)
            m = fmaxf(m, __shfl_xor_sync(0xffffffff, m, off));
        float inv = (m > 0.f) ? (127.0f / m) : 0.0f;
        int q0 = __float2int_rn(v0 * inv);
        int q1 = __float2int_rn(v1 * inv);
        int q2 = __float2int_rn(v2 * inv);
        int q3 = __float2int_rn(v3 * inv);
        g_h1q[node * 32 + lane] = (unsigned)q0 | ((unsigned)q1 << 8) |
                                  ((unsigned)q2 << 16) | ((unsigned)q3 << 24);
        if (lane == 0)
            g_hscl[node] = m * g_dinv[node] * (1.0f / 127.0f);
    }
}

// int8 dequant: PRMT builds fp32 pattern 8388608+b; subtract; FFMA. No cvt pipe.
__device__ __forceinline__ void dq_fma(float4& r, unsigned v, float s) {
    float f0 = __int_as_float(__byte_perm(v, 0x4B000000, 0x7440)) - 8388608.0f;
    float f1 = __int_as_float(__byte_perm(v, 0x4B000000, 0x7441)) - 8388608.0f;
    float f2 = __int_as_float(__byte_perm(v, 0x4B000000, 0x7442)) - 8388608.0f;
    float f3 = __int_as_float(__byte_perm(v, 0x4B000000, 0x7443)) - 8388608.0f;
    r.x += s * f0; r.y += s * f1; r.z += s * f2; r.w += s * f3;
}

// agg2: warp handles NPW consecutive nodes; int8 gather; batched pool atomics
__global__ void k_agg2(const int* __restrict__ batch) {
    int warp = (blockIdx.x * blockDim.x + threadIdx.x) >> 5;
    int lane = threadIdx.x & 31;
    int n0 = warp * NPW;
    if (n0 >= NN) return;
    int nend = n0 + NPW; if (nend > NN) nend = NN;
    float4 acc = make_float4(0.f, 0.f, 0.f, 0.f);
    int cur_b = batch[n0];
    for (int node = n0; node < nend; node++) {
        int b = batch[node];
        if (b != cur_b) {
            float* p = &g_pool[cur_b * HID + lane * 4];
            atomicAdd(p + 0, acc.x); atomicAdd(p + 1, acc.y);
            atomicAdd(p + 2, acc.z); atomicAdd(p + 3, acc.w);
            acc = make_float4(0.f, 0.f, 0.f, 0.f);
            cur_b = b;
        }
        int beg = g_off[node] + g_bpre[node >> 10];
        int end = g_off[node + 1] + g_bpre[(node + 1) >> 10];
        float4 r = make_float4(0.f, 0.f, 0.f, 0.f);
        int j = beg;
        for (; j + 3 < end; j += 4) {
            int c0 = g_col[j], c1 = g_col[j+1], c2 = g_col[j+2], c3 = g_col[j+3];
            unsigned v0 = g_h1q[c0 * 32 + lane];
            unsigned v1 = g_h1q[c1 * 32 + lane];
            unsigned v2 = g_h1q[c2 * 32 + lane];
            unsigned v3 = g_h1q[c3 * 32 + lane];
            float s0 = g_hscl[c0], s1 = g_hscl[c1];
            float s2 = g_hscl[c2], s3 = g_hscl[c3];
            dq_fma(r, v0, s0); dq_fma(r, v1, s1);
            dq_fma(r, v2, s2); dq_fma(r, v3, s3);
        }
        for (; j < end; j++) {
            int c = g_col[j];
            dq_fma(r, g_h1q[c * 32 + lane], g_hscl[c]);
        }
        float di = g_dinv[node];
        acc.x += di * r.x; acc.y += di * r.y;
        acc.z += di * r.z; acc.w += di * r.w;
    }
    float* p = &g_pool[cur_b * HID + lane * 4];
    atomicAdd(p + 0, acc.x); atomicAdd(p + 1, acc.y);
    atomicAdd(p + 2, acc.z); atomicAdd(p + 3, acc.w);
}

// out[g] = (pool[g]/cnt) @ Wf + bf
__global__ void k_out(const float* __restrict__ blin, float* __restrict__ out) {
    int warp = (blockIdx.x * blockDim.x + threadIdx.x) >> 5;
    int lane = threadIdx.x & 31;
    if (warp >= NG || lane >= FOUT) return;
    int cnt = g_gstart[warp + 1] - g_gstart[warp];
    float inv = (cnt > 0) ? (1.0f / (float)cnt) : 0.0f;
    float acc = (cnt > 0) ? g_bf[lane] : blin[lane];
    for (int f = 0; f < HID; f++)
        acc += (g_pool[warp * HID + f] * inv) * g_wf[f * FOUT + lane];
    out[warp * FOUT + lane] = acc;
}

extern "C" void kernel_launch(void* const* d_in, const int* in_sizes, int n_in,
                              void* d_out, int out_size) {
    const float* x    = (const float*)d_in[0];
    const int*   esrc = (const int*)d_in[1];
    const int*   edst = (const int*)d_in[2];
    const int*   batch= (const int*)d_in[3];
    const float* W1   = (const float*)d_in[4];
    const float* b1   = (const float*)d_in[5];
    const float* W2   = (const float*)d_in[6];
    const float* b2   = (const float*)d_in[7];
    const float* Wlin = (const float*)d_in[8];
    const float* blin = (const float*)d_in[9];
    float* out = (float*)d_out;

    k_deg  <<<EDGE_BLKS + POOL_BLKS + FUSE_BLKS, 256>>>(edst, W2, Wlin, b2, blin);
    k_scanA<<<NB, SCAN_B>>>(batch, x);
    k_scanB<<<1, 1024>>>();
    k_fill <<<(NT + 255) / 256, 256>>>(esrc, edst);
    k_agg1 <<<(NN * 32 + 255) / 256, 256>>>();
    k_gemm1<<<G2_BLK, 256>>>(W1, b1);
    {
        int warps = (NN + NPW - 1) / NPW;
        k_agg2 <<<(warps * 32 + 255) / 256, 256>>>(batch);
    }
    k_out  <<<(NG * 32 + 255) / 256, 256>>>(blin, out);
}

// round 10
// speedup vs baseline: 1.1697x; 1.1697x over previous
#include <cuda_runtime.h>
#include <cuda_bf16.h>
#include <cuda_fp16.h>

#define NN   100000
#define NE   1600000
#define NG   4096
#define HID  128
#define FIN  11
#define FPAD 16
#define FOUT 19
#define NT   (NE + NN)   // edges + self loops
#define SCAN_B 1024
#define NB   ((NN + SCAN_B - 1) / SCAN_B)   // 98
#define EDGE_BLKS ((NE + 255) / 256)        // 6250
#define FUSE_BLKS 10
#define POOL_BLKS ((NG * HID) / 256)        // 2048
#define NPW  8           // nodes per warp in agg2

// ---- scratch (static device globals; no allocation) ----
// Invariant: g_cnt and g_gcnt are all-zero at entry (BSS zero on first call;
// reset inside scanA/scanB each call). g_pool zeroed by k_deg tail blocks.
__device__ int   g_cnt[NN];
__device__ float g_dinv[NN];
__device__ int   g_off[NN + 1];      // block-LOCAL exclusive offsets
__device__ int   g_col[NT];
__device__ int   g_rank[NE];         // edge's slot within its dst node (from k_deg)
__device__ int   g_bsum[NB];
__device__ int   g_bpre[NB];         // block prefixes (add to local offsets)
__device__ int   g_gcnt[NG];
__device__ int   g_gstart[NG + 1];   // node range per graph (batch is sorted)
__device__ __align__(16) __half g_xsh[NN * FPAD];   // dinv[i]*x[i], fp16, padded
__device__ __align__(16) float g_agg1[NN * FPAD];
__device__ __align__(16) __half g_h1h[NN * HID];    // dinv[i]*relu(h1), fp16
__device__ __align__(16) float g_pool[NG * HID];
__device__ float g_wf[HID * FOUT];
__device__ float g_bf[FOUT];

// ---- deg+rank (edge blocks) + weight precompute + pool zeroing (tail blocks) ----
__global__ void k_deg(const int* __restrict__ dst,
                      const float* __restrict__ W2, const float* __restrict__ Wlin,
                      const float* __restrict__ b2, const float* __restrict__ blin) {
    int b = blockIdx.x;
    if (b < EDGE_BLKS) {
        int e = b * 256 + threadIdx.x;
        if (e < NE) g_rank[e] = atomicAdd(&g_cnt[dst[e]], 1);
    } else if (b < EDGE_BLKS + POOL_BLKS) {
        int t = (b - EDGE_BLKS) * 256 + threadIdx.x;
        g_pool[t] = 0.0f;
    } else {
        int t = (b - EDGE_BLKS - POOL_BLKS) * 256 + threadIdx.x;
        if (t < HID * FOUT) {
            int f = t / FOUT, o = t % FOUT;
            float acc = 0.0f;
            for (int m = 0; m < HID; m++) acc += W2[f * HID + m] * Wlin[m * FOUT + o];
            g_wf[t] = acc;
        }
        if (t < FOUT) {
            float acc = blin[t];
            for (int m = 0; m < HID; m++) acc += b2[m] * Wlin[m * FOUT + t];
            g_bf[t] = acc;
        }
    }
}

// ---- scanA: per-block local scan of (deg+1), fused dinv/xs/graph-count; resets g_cnt ----
__global__ void k_scanA(const int* __restrict__ batch, const float* __restrict__ x) {
    __shared__ int s[SCAN_B];
    int t = threadIdx.x;
    int i = blockIdx.x * SCAN_B + t;
    int c = 0;
    if (i < NN) {
        c = g_cnt[i] + 1;              // +1 self-loop
        g_cnt[i] = 0;                  // restore invariant for next call
        float di = rsqrtf((float)c);
        g_dinv[i] = di;
        atomicAdd(&g_gcnt[batch[i]], 1);
        __half* row = &g_xsh[i * FPAD];
#pragma unroll
        for (int k = 0; k < FIN; k++) row[k] = __float2half(di * x[i * FIN + k]);
#pragma unroll
        for (int k = FIN; k < FPAD; k++) row[k] = __float2half(0.0f);
    }
    s[t] = c;
    __syncthreads();
#pragma unroll
    for (int off = 1; off < SCAN_B; off <<= 1) {
        int v = (t >= off) ? s[t - off] : 0;
        __syncthreads();
        if (t >= off) s[t] += v;
        __syncthreads();
    }
    if (i < NN) g_off[i] = s[t] - c;
    else if (i == NN) g_off[NN] = s[t];   // c==0 → local total
    if (t == SCAN_B - 1) g_bsum[blockIdx.x] = s[t];
}

// ---- scanB: scan block sums -> g_bpre; scan g_gcnt -> g_gstart; resets g_gcnt ----
__global__ void k_scanB() {
    __shared__ int s[1024];
    int t = threadIdx.x;
    int v = (t < NB) ? g_bsum[t] : 0;
    s[t] = v;
    __syncthreads();
#pragma unroll
    for (int off = 1; off < 1024; off <<= 1) {
        int u = (t >= off) ? s[t - off] : 0;
        __syncthreads();
        if (t >= off) s[t] += u;
        __syncthreads();
    }
    if (t < NB) g_bpre[t] = s[t] - v;
    __syncthreads();
    int base = t * 4;
    int c0 = g_gcnt[base + 0], c1 = g_gcnt[base + 1];
    int c2 = g_gcnt[base + 2], c3 = g_gcnt[base + 3];
    g_gcnt[base + 0] = 0; g_gcnt[base + 1] = 0;
    g_gcnt[base + 2] = 0; g_gcnt[base + 3] = 0;
    int tsum = c0 + c1 + c2 + c3;
    s[t] = tsum;
    __syncthreads();
#pragma unroll
    for (int off = 1; off < 1024; off <<= 1) {
        int u = (t >= off) ? s[t - off] : 0;
        __syncthreads();
        if (t >= off) s[t] += u;
        __syncthreads();
    }
    int excl = s[t] - tsum;
    g_gstart[base + 0] = excl;
    g_gstart[base + 1] = excl + c0;
    g_gstart[base + 2] = excl + c0 + c1;
    g_gstart[base + 3] = excl + c0 + c1 + c2;
    if (t == 1023) g_gstart[NG] = s[t];   // == NN
}

// ---- fill: NO atomics — slot = global_off[dst] + precomputed rank ----
__global__ void k_fill(const int* __restrict__ src, const int* __restrict__ dst) {
    int t = blockIdx.x * blockDim.x + threadIdx.x;
    if (t >= NT) return;
    if (t < NE) {
        int d = dst[t];
        int p = g_off[d] + g_bpre[d >> 10] + g_rank[t];
        g_col[p] = src[t];
    } else {
        int d = t - NE;       // self-loop goes in the node's last slot
        int p = g_off[d + 1] + g_bpre[(d + 1) >> 10] - 1;
        g_col[p] = d;
    }
}

// agg1[i] = dinv[i] * sum_j xs[col[j]]; lane = 8*e + f
__global__ void k_agg1() {
    int warp = (blockIdx.x * blockDim.x + threadIdx.x) >> 5;
    int lane = threadIdx.x & 31;
    if (warp >= NN) return;
    int beg = g_off[warp] + g_bpre[warp >> 10];
    int end = g_off[warp + 1] + g_bpre[(warp + 1) >> 10];
    int e = lane >> 3, f = lane & 7;
    const __half2* xs2 = (const __half2*)g_xsh;
    float2 acc = make_float2(0.f, 0.f);
    for (int j = beg + e; j < end; j += 4) {
        float2 a = __half22float2(xs2[g_col[j] * 8 + f]);
        acc.x += a.x; acc.y += a.y;
    }
    acc.x += __shfl_xor_sync(0xffffffff, acc.x, 8);
    acc.y += __shfl_xor_sync(0xffffffff, acc.y, 8);
    acc.x += __shfl_xor_sync(0xffffffff, acc.x, 16);
    acc.y += __shfl_xor_sync(0xffffffff, acc.y, 16);
    if (lane < 8) {
        float di = g_dinv[warp];
        ((float2*)&g_agg1[warp * FPAD])[f] = make_float2(di * acc.x, di * acc.y);
    }
}

// h1 = dinv * relu(agg1 @ W1 + b1) stored fp16; 128 threads, 64 nodes/block
#define GB_NODES 64
__global__ void k_gemm1(const float* __restrict__ W1, const float* __restrict__ b1) {
    __shared__ float sW[FIN * HID];
    __shared__ float sb[HID];
    __shared__ float srow[GB_NODES * FIN];
    __shared__ float sdi[GB_NODES];
    int t = threadIdx.x;
    for (int k = t; k < FIN * HID; k += 128) sW[k] = W1[k];
    sb[t] = b1[t];
    int nb = blockIdx.x * GB_NODES;
    for (int k = t; k < GB_NODES * FIN; k += 128) {
        int node = nb + k / FIN;
        srow[k] = (node < NN) ? g_agg1[node * FPAD + (k % FIN)] : 0.0f;
    }
    for (int k = t; k < GB_NODES; k += 128) {
        int node = nb + k;
        sdi[k] = (node < NN) ? g_dinv[node] : 0.0f;
    }
    __syncthreads();
    float wc[FIN];
#pragma unroll
    for (int k = 0; k < FIN; k++) wc[k] = sW[k * HID + t];
    for (int n = 0; n < GB_NODES; n++) {
        int node = nb + n;
        if (node >= NN) break;
        float acc = sb[t];
#pragma unroll
        for (int k = 0; k < FIN; k++) acc += srow[n * FIN + k] * wc[k];
        g_h1h[(size_t)node * HID + t] = __float2half(sdi[n] * fmaxf(acc, 0.0f));
    }
}

// agg2: warp handles NPW consecutive nodes; fp16 gather; batched pool atomics
__global__ void k_agg2(const int* __restrict__ batch) {
    int warp = (blockIdx.x * blockDim.x + threadIdx.x) >> 5;
    int lane = threadIdx.x & 31;
    int n0 = warp * NPW;
    if (n0 >= NN) return;
    int nend = n0 + NPW; if (nend > NN) nend = NN;
    const uint2* h2 = (const uint2*)g_h1h;   // 32 x 8B slots per 128-feat row
    float4 acc = make_float4(0.f, 0.f, 0.f, 0.f);
    int cur_b = batch[n0];
    for (int node = n0; node < nend; node++) {
        int b = batch[node];
        if (b != cur_b) {
            float* p = &g_pool[cur_b * HID + lane * 4];
            atomicAdd(p + 0, acc.x); atomicAdd(p + 1, acc.y);
            atomicAdd(p + 2, acc.z); atomicAdd(p + 3, acc.w);
            acc = make_float4(0.f, 0.f, 0.f, 0.f);
            cur_b = b;
        }
        int beg = g_off[node] + g_bpre[node >> 10];
        int end = g_off[node + 1] + g_bpre[(node + 1) >> 10];
        float4 r = make_float4(0.f, 0.f, 0.f, 0.f);
        int j = beg;
        for (; j + 3 < end; j += 4) {
            int c0 = g_col[j], c1 = g_col[j+1], c2 = g_col[j+2], c3 = g_col[j+3];
            uint2 v0 = h2[c0 * 32 + lane];
            uint2 v1 = h2[c1 * 32 + lane];
            uint2 v2 = h2[c2 * 32 + lane];
            uint2 v3 = h2[c3 * 32 + lane];
            float2 a, bb;
            a = __half22float2(*(__half2*)&v0.x); bb = __half22float2(*(__half2*)&v0.y);
            r.x += a.x; r.y += a.y; r.z += bb.x; r.w += bb.y;
            a = __half22float2(*(__half2*)&v1.x); bb = __half22float2(*(__half2*)&v1.y);
            r.x += a.x; r.y += a.y; r.z += bb.x; r.w += bb.y;
            a = __half22float2(*(__half2*)&v2.x); bb = __half22float2(*(__half2*)&v2.y);
            r.x += a.x; r.y += a.y; r.z += bb.x; r.w += bb.y;
            a = __half22float2(*(__half2*)&v3.x); bb = __half22float2(*(__half2*)&v3.y);
            r.x += a.x; r.y += a.y; r.z += bb.x; r.w += bb.y;
        }
        for (; j < end; j++) {
            uint2 v = h2[g_col[j] * 32 + lane];
            float2 a = __half22float2(*(__half2*)&v.x);
            float2 bb = __half22float2(*(__half2*)&v.y);
            r.x += a.x; r.y += a.y; r.z += bb.x; r.w += bb.y;
        }
        float di = g_dinv[node];
        acc.x += di * r.x; acc.y += di * r.y;
        acc.z += di * r.z; acc.w += di * r.w;
    }
    float* p = &g_pool[cur_b * HID + lane * 4];
    atomicAdd(p + 0, acc.x); atomicAdd(p + 1, acc.y);
    atomicAdd(p + 2, acc.z); atomicAdd(p + 3, acc.w);
}

// out[g] = (pool[g]/cnt) @ Wf + bf
__global__ void k_out(const float* __restrict__ blin, float* __restrict__ out) {
    int warp = (blockIdx.x * blockDim.x + threadIdx.x) >> 5;
    int lane = threadIdx.x & 31;
    if (warp >= NG || lane >= FOUT) return;
    int cnt = g_gstart[warp + 1] - g_gstart[warp];
    float inv = (cnt > 0) ? (1.0f / (float)cnt) : 0.0f;
    float acc = (cnt > 0) ? g_bf[lane] : blin[lane];
    for (int f = 0; f < HID; f++)
        acc += (g_pool[warp * HID + f] * inv) * g_wf[f * FOUT + lane];
    out[warp * FOUT + lane] = acc;
}

extern "C" void kernel_launch(void* const* d_in, const int* in_sizes, int n_in,
                              void* d_out, int out_size) {
    const float* x    = (const float*)d_in[0];
    const int*   esrc = (const int*)d_in[1];
    const int*   edst = (const int*)d_in[2];
    const int*   batch= (const int*)d_in[3];
    const float* W1   = (const float*)d_in[4];
    const float* b1   = (const float*)d_in[5];
    const float* W2   = (const float*)d_in[6];
    const float* b2   = (const float*)d_in[7];
    const float* Wlin = (const float*)d_in[8];
    const float* blin = (const float*)d_in[9];
    float* out = (float*)d_out;

    k_deg  <<<EDGE_BLKS + POOL_BLKS + FUSE_BLKS, 256>>>(edst, W2, Wlin, b2, blin);
    k_scanA<<<NB, SCAN_B>>>(batch, x);
    k_scanB<<<1, 1024>>>();
    k_fill <<<(NT + 255) / 256, 256>>>(esrc, edst);
    k_agg1 <<<(NN * 32 + 255) / 256, 256>>>();
    k_gemm1<<<(NN + GB_NODES - 1) / GB_NODES, 128>>>(W1, b1);
    {
        int warps = (NN + NPW - 1) / NPW;
        k_agg2 <<<(warps * 32 + 255) / 256, 256>>>(batch);
    }
    k_out  <<<(NG * 32 + 255) / 256, 256>>>(blin, out);
}

// round 13
// speedup vs baseline: 1.2022x; 1.0278x over previous
#include <cuda_runtime.h>
#include <cuda_bf16.h>
#include <cuda_fp16.h>

#define NN   100000
#define NE   1600000
#define NG   4096
#define HID  128
#define FIN  11
#define FPAD 16
#define FOUT 19
#define NT   (NE + NN)   // edges + self loops
#define SCAN_B 1024
#define NB   ((NN + SCAN_B - 1) / SCAN_B)   // 98
#define NE4  (NE / 4)                        // 400000 (NE divisible by 4)
#define EDGE_BLKS4 ((NE4 + 255) / 256)       // 1563
#define FUSE_BLKS 10
#define POOL_BLKS ((NG * HID) / 256)         // 2048
#define NPW  8           // nodes per warp in agg2

// ---- scratch (static device globals; no allocation) ----
// Invariant: g_cnt and g_gcnt are all-zero at entry (BSS zero on first call;
// reset inside scanA/scanB each call). g_pool zeroed by k_deg tail blocks.
__device__ int   g_cnt[NN];
__device__ float g_dinv[NN];
__device__ int   g_off[NN + 1];      // block-LOCAL exclusive offsets
__device__ int   g_col[NT];
__device__ __align__(16) int g_rank[NE];   // edge's slot within its dst (from k_deg)
__device__ int   g_bsum[NB];
__device__ int   g_bpre[NB];         // block prefixes (add to local offsets)
__device__ int   g_gcnt[NG];
__device__ int   g_gstart[NG + 1];   // node range per graph (batch is sorted)
__device__ __align__(16) __half g_xsh[NN * FPAD];   // dinv[i]*x[i], fp16, padded
__device__ __align__(16) __half g_h1h[NN * HID];    // dinv[i]*relu(h1), fp16
__device__ __align__(16) float g_pool[NG * HID];
__device__ float g_wf[HID * FOUT];
__device__ float g_bf[FOUT];

// ---- deg+rank (vectorized edge blocks) + weight precompute + pool zero (tail) ----
__global__ void k_deg(const int4* __restrict__ dst4,
                      const float* __restrict__ W2, const float* __restrict__ Wlin,
                      const float* __restrict__ b2, const float* __restrict__ blin) {
    int b = blockIdx.x;
    if (b < EDGE_BLKS4) {
        int t = b * 256 + threadIdx.x;
        if (t < NE4) {
            int4 d = dst4[t];
            int4 r;
            r.x = atomicAdd(&g_cnt[d.x], 1);
            r.y = atomicAdd(&g_cnt[d.y], 1);
            r.z = atomicAdd(&g_cnt[d.z], 1);
            r.w = atomicAdd(&g_cnt[d.w], 1);
            ((int4*)g_rank)[t] = r;
        }
    } else if (b < EDGE_BLKS4 + POOL_BLKS) {
        int t = (b - EDGE_BLKS4) * 256 + threadIdx.x;
        g_pool[t] = 0.0f;
    } else {
        int t = (b - EDGE_BLKS4 - POOL_BLKS) * 256 + threadIdx.x;
        if (t < HID * FOUT) {
            int f = t / FOUT, o = t % FOUT;
            float acc = 0.0f;
            for (int m = 0; m < HID; m++) acc += W2[f * HID + m] * Wlin[m * FOUT + o];
            g_wf[t] = acc;
        }
        if (t < FOUT) {
            float acc = blin[t];
            for (int m = 0; m < HID; m++) acc += b2[m] * Wlin[m * FOUT + t];
            g_bf[t] = acc;
        }
    }
}

// ---- scanA: per-block local scan of (deg+1), fused dinv/xs/graph-count; resets g_cnt ----
__global__ void k_scanA(const int* __restrict__ batch, const float* __restrict__ x) {
    __shared__ int s[SCAN_B];
    int t = threadIdx.x;
    int i = blockIdx.x * SCAN_B + t;
    int c = 0;
    if (i < NN) {
        c = g_cnt[i] + 1;              // +1 self-loop
        g_cnt[i] = 0;                  // restore invariant for next call
        float di = rsqrtf((float)c);
        g_dinv[i] = di;
        atomicAdd(&g_gcnt[batch[i]], 1);
        __half* row = &g_xsh[i * FPAD];
#pragma unroll
        for (int k = 0; k < FIN; k++) row[k] = __float2half(di * x[i * FIN + k]);
#pragma unroll
        for (int k = FIN; k < FPAD; k++) row[k] = __float2half(0.0f);
    }
    s[t] = c;
    __syncthreads();
#pragma unroll
    for (int off = 1; off < SCAN_B; off <<= 1) {
        int v = (t >= off) ? s[t - off] : 0;
        __syncthreads();
        if (t >= off) s[t] += v;
        __syncthreads();
    }
    if (i < NN) g_off[i] = s[t] - c;
    else if (i == NN) g_off[NN] = s[t];   // c==0 → local total
    if (t == SCAN_B - 1) g_bsum[blockIdx.x] = s[t];
}

// ---- scanB: scan block sums -> g_bpre; scan g_gcnt -> g_gstart; resets g_gcnt ----
__global__ void k_scanB() {
    __shared__ int s[1024];
    int t = threadIdx.x;
    int v = (t < NB) ? g_bsum[t] : 0;
    s[t] = v;
    __syncthreads();
#pragma unroll
    for (int off = 1; off < 1024; off <<= 1) {
        int u = (t >= off) ? s[t - off] : 0;
        __syncthreads();
        if (t >= off) s[t] += u;
        __syncthreads();
    }
    if (t < NB) g_bpre[t] = s[t] - v;
    __syncthreads();
    int base = t * 4;
    int c0 = g_gcnt[base + 0], c1 = g_gcnt[base + 1];
    int c2 = g_gcnt[base + 2], c3 = g_gcnt[base + 3];
    g_gcnt[base + 0] = 0; g_gcnt[base + 1] = 0;
    g_gcnt[base + 2] = 0; g_gcnt[base + 3] = 0;
    int tsum = c0 + c1 + c2 + c3;
    s[t] = tsum;
    __syncthreads();
#pragma unroll
    for (int off = 1; off < 1024; off <<= 1) {
        int u = (t >= off) ? s[t - off] : 0;
        __syncthreads();
        if (t >= off) s[t] += u;
        __syncthreads();
    }
    int excl = s[t] - tsum;
    g_gstart[base + 0] = excl;
    g_gstart[base + 1] = excl + c0;
    g_gstart[base + 2] = excl + c0 + c1;
    g_gstart[base + 3] = excl + c0 + c1 + c2;
    if (t == 1023) g_gstart[NG] = s[t];   // == NN
}

// ---- fill: NO atomics; vectorized 4 edges/thread; self-loops in tail threads ----
__global__ void k_fill(const int4* __restrict__ src4, const int4* __restrict__ dst4) {
    int t = blockIdx.x * blockDim.x + threadIdx.x;
    if (t < NE4) {
        int4 s = src4[t];
        int4 d = dst4[t];
        int4 r = ((const int4*)g_rank)[t];
        g_col[g_off[d.x] + g_bpre[d.x >> 10] + r.x] = s.x;
        g_col[g_off[d.y] + g_bpre[d.y >> 10] + r.y] = s.y;
        g_col[g_off[d.z] + g_bpre[d.z >> 10] + r.z] = s.z;
        g_col[g_off[d.w] + g_bpre[d.w >> 10] + r.w] = s.w;
    } else if (t < NE4 + NN) {
        int d = t - NE4;      // self-loop goes in the node's last slot
        int p = g_off[d + 1] + g_bpre[(d + 1) >> 10] - 1;
        g_col[p] = d;
    }
}

// ---- fused agg1 + gemm1: warp per node ----
// gather xs over CSR (all lanes), shuffle-reduce, broadcast 11-vector,
// each lane computes 4 hidden features, relu, ×dinv, store fp16 row slot.
__global__ void k_hid(const float* __restrict__ W1, const float* __restrict__ b1) {
    __shared__ float sW[FIN * HID];
    __shared__ float sb[HID];
    int t = threadIdx.x;
    for (int k = t; k < FIN * HID; k += 1024) sW[k] = W1[k];
    if (t < HID) sb[t] = b1[t];
    __syncthreads();
    int warp = (blockIdx.x * 1024 + t) >> 5;   // 3125 blocks * 32 warps = 100000
    int lane = t & 31;
    int beg = g_off[warp] + g_bpre[warp >> 10];
    int end = g_off[warp + 1] + g_bpre[(warp + 1) >> 10];
    int e = lane >> 3, f = lane & 7;
    const __half2* xs2 = (const __half2*)g_xsh;
    float2 acc = make_float2(0.f, 0.f);
    for (int j = beg + e; j < end; j += 4) {
        float2 a = __half22float2(xs2[g_col[j] * 8 + f]);
        acc.x += a.x; acc.y += a.y;
    }
    acc.x += __shfl_xor_sync(0xffffffff, acc.x, 8);
    acc.y += __shfl_xor_sync(0xffffffff, acc.y, 8);
    acc.x += __shfl_xor_sync(0xffffffff, acc.x, 16);
    acc.y += __shfl_xor_sync(0xffffffff, acc.y, 16);
    // broadcast features 0..11 (11 real; 11th is zero padding)
    float a[12];
#pragma unroll
    for (int p = 0; p < 6; p++) {
        a[2 * p]     = __shfl_sync(0xffffffff, acc.x, p);
        a[2 * p + 1] = __shfl_sync(0xffffffff, acc.y, p);
    }
    float di = g_dinv[warp];
#pragma unroll
    for (int k = 0; k < FIN; k++) a[k] *= di;   // agg1 = di * sum
    const float4* sW4 = (const float4*)sW;
    float4 v = ((const float4*)sb)[lane];
#pragma unroll
    for (int k = 0; k < FIN; k++) {
        float4 w = sW4[k * 32 + lane];
        v.x += a[k] * w.x; v.y += a[k] * w.y;
        v.z += a[k] * w.z; v.w += a[k] * w.w;
    }
    __half2 lo = __floats2half2_rn(di * fmaxf(v.x, 0.f), di * fmaxf(v.y, 0.f));
    __half2 hi = __floats2half2_rn(di * fmaxf(v.z, 0.f), di * fmaxf(v.w, 0.f));
    uint2 o;
    o.x = *(unsigned*)&lo;
    o.y = *(unsigned*)&hi;
    ((uint2*)g_h1h)[warp * 32 + lane] = o;
}

// agg2: warp handles NPW consecutive nodes; fp16 gather; batched pool atomics
__global__ void k_agg2(const int* __restrict__ batch) {
    int warp = (blockIdx.x * blockDim.x + threadIdx.x) >> 5;
    int lane = threadIdx.x & 31;
    int n0 = warp * NPW;
    if (n0 >= NN) return;
    int nend = n0 + NPW; if (nend > NN) nend = NN;
    const uint2* h2 = (const uint2*)g_h1h;   // 32 x 8B slots per 128-feat row
    float4 acc = make_float4(0.f, 0.f, 0.f, 0.f);
    int cur_b = batch[n0];
    for (int node = n0; node < nend; node++) {
        int b = batch[node];
        if (b != cur_b) {
            float* p = &g_pool[cur_b * HID + lane * 4];
            atomicAdd(p + 0, acc.x); atomicAdd(p + 1, acc.y);
            atomicAdd(p + 2, acc.z); atomicAdd(p + 3, acc.w);
            acc = make_float4(0.f, 0.f, 0.f, 0.f);
            cur_b = b;
        }
        int beg = g_off[node] + g_bpre[node >> 10];
        int end = g_off[node + 1] + g_bpre[(node + 1) >> 10];
        float4 r = make_float4(0.f, 0.f, 0.f, 0.f);
        int j = beg;
        for (; j + 3 < end; j += 4) {
            int c0 = g_col[j], c1 = g_col[j+1], c2 = g_col[j+2], c3 = g_col[j+3];
            uint2 v0 = h2[c0 * 32 + lane];
            uint2 v1 = h2[c1 * 32 + lane];
            uint2 v2 = h2[c2 * 32 + lane];
            uint2 v3 = h2[c3 * 32 + lane];
            float2 a, bb;
            a = __half22float2(*(__half2*)&v0.x); bb = __half22float2(*(__half2*)&v0.y);
            r.x += a.x; r.y += a.y; r.z += bb.x; r.w += bb.y;
            a = __half22float2(*(__half2*)&v1.x); bb = __half22float2(*(__half2*)&v1.y);
            r.x += a.x; r.y += a.y; r.z += bb.x; r.w += bb.y;
            a = __half22float2(*(__half2*)&v2.x); bb = __half22float2(*(__half2*)&v2.y);
            r.x += a.x; r.y += a.y; r.z += bb.x; r.w += bb.y;
            a = __half22float2(*(__half2*)&v3.x); bb = __half22float2(*(__half2*)&v3.y);
            r.x += a.x; r.y += a.y; r.z += bb.x; r.w += bb.y;
        }
        for (; j < end; j++) {
            uint2 v = h2[g_col[j] * 32 + lane];
            float2 a = __half22float2(*(__half2*)&v.x);
            float2 bb = __half22float2(*(__half2*)&v.y);
            r.x += a.x; r.y += a.y; r.z += bb.x; r.w += bb.y;
        }
        float di = g_dinv[node];
        acc.x += di * r.x; acc.y += di * r.y;
        acc.z += di * r.z; acc.w += di * r.w;
    }
    float* p = &g_pool[cur_b * HID + lane * 4];
    atomicAdd(p + 0, acc.x); atomicAdd(p + 1, acc.y);
    atomicAdd(p + 2, acc.z); atomicAdd(p + 3, acc.w);
}

// out[g] = (pool[g]/cnt) @ Wf + bf
__global__ void k_out(const float* __restrict__ blin, float* __restrict__ out) {
    int warp = (blockIdx.x * blockDim.x + threadIdx.x) >> 5;
    int lane = threadIdx.x & 31;
    if (warp >= NG || lane >= FOUT) return;
    int cnt = g_gstart[warp + 1] - g_gstart[warp];
    float inv = (cnt > 0) ? (1.0f / (float)cnt) : 0.0f;
    float acc = (cnt > 0) ? g_bf[lane] : blin[lane];
    for (int f = 0; f < HID; f++)
        acc += (g_pool[warp * HID + f] * inv) * g_wf[f * FOUT + lane];
    out[warp * FOUT + lane] = acc;
}

extern "C" void kernel_launch(void* const* d_in, const int* in_sizes, int n_in,
                              void* d_out, int out_size) {
    const float* x    = (const float*)d_in[0];
    const int*   esrc = (const int*)d_in[1];
    const int*   edst = (const int*)d_in[2];
    const int*   batch= (const int*)d_in[3];
    const float* W1   = (const float*)d_in[4];
    const float* b1   = (const float*)d_in[5];
    const float* W2   = (const float*)d_in[6];
    const float* b2   = (const float*)d_in[7];
    const float* Wlin = (const float*)d_in[8];
    const float* blin = (const float*)d_in[9];
    float* out = (float*)d_out;

    k_deg  <<<EDGE_BLKS4 + POOL_BLKS + FUSE_BLKS, 256>>>((const int4*)edst, W2, Wlin, b2, blin);
    k_scanA<<<NB, SCAN_B>>>(batch, x);
    k_scanB<<<1, 1024>>>();
    k_fill <<<(NE4 + NN + 255) / 256, 256>>>((const int4*)esrc, (const int4*)edst);
    k_hid  <<<NN / 32, 1024>>>(W1, b1);
    {
        int warps = (NN + NPW - 1) / NPW;
        k_agg2 <<<(warps * 32 + 255) / 256, 256>>>(batch);
    }
    k_out  <<<(NG * 32 + 255) / 256, 256>>>(blin, out);
}